// round 1
// baseline (speedup 1.0000x reference)
#include <cuda_runtime.h>
#include <math.h>
#include <stdint.h>

#define SEQ    2048
#define DM     768
#define NL     4
#define DSTATE 128
#define HD     64
#define CT     64          // chunk length
#define NCH    32          // SEQ / CT
#define DIN    1536
#define NH     24
#define CONVD  1792        // DIN + 2*DSTATE
#define DPROJ  3352        // 2*DIN + 2*DSTATE + NH
#define NV     50288

// ---------------- scratch (device globals; no allocation allowed) ----------
__device__ __align__(128) float g_x[SEQ*DM];        // residual stream
__device__ __align__(128) float g_u[SEQ*DM];        // normed input / final normed
__device__ __align__(128) float g_zx[SEQ*DPROJ];    // in_proj output
__device__ __align__(128) float g_xBC[SEQ*CONVD];   // conv+silu output
__device__ __align__(128) float g_dt[SEQ*NH];
__device__ __align__(128) float g_Adt[SEQ*NH];
__device__ __align__(128) float g_acs[SEQ*NH];      // per-chunk inclusive cumsum of A*dt
__device__ __align__(128) float g_Asum[NCH*NH];
__device__ __align__(128) float g_xdt[SEQ*DIN];
__device__ __align__(128) float g_states[NCH*NH*HD*DSTATE];
__device__ __align__(128) float g_y[SEQ*DIN];
__device__ __align__(128) float g_yn[SEQ*DIN];

// ---------------- helpers ----------------
__device__ __forceinline__ float block_sum(float v) {
    __shared__ float red[256];
    int t = threadIdx.x;
    red[t] = v; __syncthreads();
    for (int s = 128; s > 0; s >>= 1) {
        if (t < s) red[t] += red[t + s];
        __syncthreads();
    }
    float r = red[0];
    __syncthreads();
    return r;
}

// ---------------- embedding gather ----------------
__global__ void embed_kernel(const int* __restrict__ ids, const float* __restrict__ emb) {
    int l = blockIdx.x;
    int id = ids[l];
    for (int d = threadIdx.x; d < DM; d += 256)
        g_x[(size_t)l*DM + d] = emb[(size_t)id*DM + d];
}

// ---------------- rmsnorm (no gate) ----------------
__global__ void rmsnorm_kernel(const float* __restrict__ in, const float* __restrict__ w,
                               float* __restrict__ out, int D) {
    int row = blockIdx.x;
    const float* x = in + (size_t)row*D;
    float s = 0.f;
    for (int i = threadIdx.x; i < D; i += 256) { float v = x[i]; s += v*v; }
    float tot = block_sum(s);
    float sc = rsqrtf(tot / (float)D + 1e-5f);
    for (int i = threadIdx.x; i < D; i += 256)
        out[(size_t)row*D + i] = x[i] * sc * w[i];
}

// ---------------- gated rmsnorm (z from g_zx, y from g_y -> g_yn) ----------
__global__ void gated_rmsnorm_kernel(const float* __restrict__ w) {
    int row = blockIdx.x;
    __shared__ float tbuf[DIN];
    float s = 0.f;
    for (int i = threadIdx.x; i < DIN; i += 256) {
        float v = g_y[(size_t)row*DIN + i];
        float z = g_zx[(size_t)row*DPROJ + i];
        float g = v * (z / (1.f + expf(-z)));
        tbuf[i] = g; s += g*g;
    }
    float tot = block_sum(s);
    float sc = rsqrtf(tot / (float)DIN + 1e-5f);
    for (int i = threadIdx.x; i < DIN; i += 256)
        g_yn[(size_t)row*DIN + i] = tbuf[i] * sc * w[i];
}

// ---------------- SGEMM: C = A(MxK,row) * W(NxK,row)^T (+ addsrc) ----------
// 128x128 tile, BK=8, 256 threads, 8x8 per thread.
__global__ void __launch_bounds__(256)
gemm_kernel(const float* __restrict__ A, const float* __restrict__ W,
            const float* __restrict__ addsrc, float* __restrict__ C,
            int M, int N, int K) {
    __shared__ float As[8][132];
    __shared__ float Bs[8][132];
    const int tid = threadIdx.x;
    const int m0 = blockIdx.y * 128;
    const int n0 = blockIdx.x * 128;
    const int tr = tid >> 4;         // 0..15
    const int tc = tid & 15;         // 0..15
    const int lrow = tid >> 1;       // 0..127
    const int lk   = (tid & 1) * 4;  // 0 or 4

    float acc[8][8];
#pragma unroll
    for (int i = 0; i < 8; i++)
#pragma unroll
        for (int j = 0; j < 8; j++) acc[i][j] = 0.f;

    const int arow = m0 + lrow;
    const int brow = n0 + lrow;
    const bool a_ok = arow < M;
    const bool b_ok = brow < N;
    const float* Aptr = A + (size_t)arow*K + lk;
    const float* Wptr = W + (size_t)brow*K + lk;

    for (int k0 = 0; k0 < K; k0 += 8) {
        float4 av = make_float4(0.f,0.f,0.f,0.f);
        float4 bv = make_float4(0.f,0.f,0.f,0.f);
        if (a_ok) av = *(const float4*)(Aptr + k0);
        if (b_ok) bv = *(const float4*)(Wptr + k0);
        As[lk+0][lrow] = av.x; As[lk+1][lrow] = av.y;
        As[lk+2][lrow] = av.z; As[lk+3][lrow] = av.w;
        Bs[lk+0][lrow] = bv.x; Bs[lk+1][lrow] = bv.y;
        Bs[lk+2][lrow] = bv.z; Bs[lk+3][lrow] = bv.w;
        __syncthreads();
#pragma unroll
        for (int k = 0; k < 8; k++) {
            float ra[8], rb[8];
            *(float4*)&ra[0] = *(const float4*)&As[k][tr*8];
            *(float4*)&ra[4] = *(const float4*)&As[k][tr*8+4];
            *(float4*)&rb[0] = *(const float4*)&Bs[k][tc*8];
            *(float4*)&rb[4] = *(const float4*)&Bs[k][tc*8+4];
#pragma unroll
            for (int i = 0; i < 8; i++)
#pragma unroll
                for (int j = 0; j < 8; j++) acc[i][j] += ra[i]*rb[j];
        }
        __syncthreads();
    }
#pragma unroll
    for (int i = 0; i < 8; i++) {
        int m = m0 + tr*8 + i;
        if (m >= M) continue;
#pragma unroll
        for (int j = 0; j < 8; j++) {
            int n = n0 + tc*8 + j;
            if (n >= N) continue;
            float v = acc[i][j];
            if (addsrc) v += addsrc[(size_t)m*N + n];
            C[(size_t)m*N + n] = v;
        }
    }
}

// ---------------- depthwise causal conv + silu ----------------
__global__ void conv_kernel(const float* __restrict__ cw, const float* __restrict__ cb) {
    int idx = blockIdx.x*256 + threadIdx.x;
    if (idx >= SEQ*CONVD) return;
    int l = idx / CONVD, ch = idx % CONVD;
    float s = cb[ch];
#pragma unroll
    for (int k = 0; k < 4; k++) {
        int t = l - 3 + k;
        if (t >= 0) s += cw[ch*4 + k] * g_zx[(size_t)t*DPROJ + DIN + ch];
    }
    g_xBC[idx] = s / (1.f + expf(-s));   // silu
}

// ---------------- dt = softplus(raw + bias); Adt = -exp(A_log)*dt ----------
__global__ void dt_kernel(const float* __restrict__ dtb, const float* __restrict__ alog) {
    int idx = blockIdx.x*256 + threadIdx.x;
    if (idx >= SEQ*NH) return;
    int h = idx % NH;
    float v = g_zx[(size_t)(idx/NH)*DPROJ + DIN + CONVD + h] + dtb[h];
    float dt = (v > 20.f) ? v : log1pf(expf(v));
    g_dt[idx] = dt;
    g_Adt[idx] = -expf(alog[h]) * dt;
}

// ---------------- xdt = x * dt ----------------
__global__ void pack_kernel() {
    int idx = blockIdx.x*256 + threadIdx.x;   // exact SEQ*DIN
    int l = idx / DIN, i = idx % DIN;
    g_xdt[idx] = g_xBC[(size_t)l*CONVD + i] * g_dt[l*NH + i/HD];
}

// ---------------- per-(chunk, head): G mask, Y_diag, per-chunk states ------
__global__ void __launch_bounds__(256)
chunk_kernel() {
    extern __shared__ float sm[];
    float* sB   = sm;                  // 64*129
    float* sC   = sB + 64*129;         // 64*129
    float* sX   = sC + 64*129;         // 64*65
    float* sM   = sX + 64*65;          // 64*65
    float* sAcs = sM + 64*65;          // 64
    float* sDec = sAcs + 64;           // 64

    const int c = blockIdx.x, h = blockIdx.y, tid = threadIdx.x;

    for (int idx = tid; idx < 64*128; idx += 256) {
        int r = idx >> 7, n = idx & 127;
        const float* row = g_xBC + (size_t)(c*64 + r)*CONVD + DIN;
        sB[r*129 + n] = row[n];
        sC[r*129 + n] = row[DSTATE + n];
    }
    for (int idx = tid; idx < 64*64; idx += 256) {
        int r = idx >> 6, p = idx & 63;
        sX[r*65 + p] = g_xdt[(size_t)(c*64 + r)*DIN + h*HD + p];
    }
    if (tid == 0) {
        float run = 0.f;
        for (int t = 0; t < 64; t++) {
            run += g_Adt[(c*64 + t)*NH + h];
            sAcs[t] = run;
            g_acs[(c*64 + t)*NH + h] = run;
        }
        g_Asum[c*NH + h] = run;
    }
    __syncthreads();
    if (tid < 64) sDec[tid] = expf(sAcs[63] - sAcs[tid]);
    __syncthreads();

    // G = C B^T with causal decay mask -> sM
    {
        const int i0 = (tid & 15)*4, j0 = (tid >> 4)*4;
        float acc[4][4] = {};
        for (int n = 0; n < 128; n++) {
            float a[4], b[4];
#pragma unroll
            for (int ii = 0; ii < 4; ii++) a[ii] = sC[(i0+ii)*129 + n];
#pragma unroll
            for (int jj = 0; jj < 4; jj++) b[jj] = sB[(j0+jj)*129 + n];
#pragma unroll
            for (int ii = 0; ii < 4; ii++)
#pragma unroll
                for (int jj = 0; jj < 4; jj++) acc[ii][jj] += a[ii]*b[jj];
        }
#pragma unroll
        for (int ii = 0; ii < 4; ii++)
#pragma unroll
            for (int jj = 0; jj < 4; jj++) {
                int i = i0 + ii, j = j0 + jj;
                sM[i*65 + j] = (j <= i) ? acc[ii][jj]*expf(sAcs[i] - sAcs[j]) : 0.f;
            }
    }
    __syncthreads();

    // Y_diag = M @ X  -> g_y
    {
        const int i0 = (tid & 15)*4, p0 = (tid >> 4)*4;
        float acc[4][4] = {};
        for (int j = 0; j < 64; j++) {
            float m[4], xv[4];
#pragma unroll
            for (int ii = 0; ii < 4; ii++) m[ii] = sM[(i0+ii)*65 + j];
#pragma unroll
            for (int jj = 0; jj < 4; jj++) xv[jj] = sX[j*65 + p0 + jj];
#pragma unroll
            for (int ii = 0; ii < 4; ii++)
#pragma unroll
                for (int jj = 0; jj < 4; jj++) acc[ii][jj] += m[ii]*xv[jj];
        }
#pragma unroll
        for (int ii = 0; ii < 4; ii++)
#pragma unroll
            for (int jj = 0; jj < 4; jj++)
                g_y[(size_t)(c*64 + i0 + ii)*DIN + h*HD + p0 + jj] = acc[ii][jj];
    }

    // states[p][n] = sum_j dec[j] * X[j][p] * B[j][n]
    {
        const int p0 = (tid & 15)*4, n0 = (tid >> 4)*8;
        float acc[4][8] = {};
        for (int j = 0; j < 64; j++) {
            float d = sDec[j];
            float xv[4], bv[8];
#pragma unroll
            for (int ii = 0; ii < 4; ii++) xv[ii] = sX[j*65 + p0 + ii]*d;
#pragma unroll
            for (int jj = 0; jj < 8; jj++) bv[jj] = sB[j*129 + n0 + jj];
#pragma unroll
            for (int ii = 0; ii < 4; ii++)
#pragma unroll
                for (int jj = 0; jj < 8; jj++) acc[ii][jj] += xv[ii]*bv[jj];
        }
#pragma unroll
        for (int ii = 0; ii < 4; ii++)
#pragma unroll
            for (int jj = 0; jj < 8; jj++)
                g_states[(size_t)((c*NH + h)*HD + p0 + ii)*DSTATE + n0 + jj] = acc[ii][jj];
    }
}

// ---------------- inter-chunk scan: states[c] <- state BEFORE chunk c ------
__global__ void scan_kernel() {
    int idx = blockIdx.x*256 + threadIdx.x;    // exact NH*HD*DSTATE
    int h = idx / (HD*DSTATE);
    int rem = idx % (HD*DSTATE);
    float S = 0.f;
    for (int c = 0; c < NCH; c++) {
        size_t off = (size_t)(c*NH + h)*HD*DSTATE + rem;
        float cur = g_states[off];
        g_states[off] = S;                       // prev state, in place
        S = expf(g_Asum[c*NH + h])*S + cur;
    }
}

// ---------------- Y_off + D-skip, accumulate into g_y ----------------------
__global__ void __launch_bounds__(256)
yoff_kernel(const float* __restrict__ Dp) {
    extern __shared__ float sm[];
    float* sC = sm;                    // 64*129
    float* sS = sC + 64*129;           // 64*129 (p-major)
    float* sA = sS + 64*129;           // 64
    const int c = blockIdx.x, h = blockIdx.y, tid = threadIdx.x;

    for (int idx = tid; idx < 64*128; idx += 256) {
        int r = idx >> 7, n = idx & 127;
        sC[r*129 + n] = g_xBC[(size_t)(c*64 + r)*CONVD + DIN + DSTATE + n];
        sS[r*129 + n] = g_states[(size_t)((c*NH + h)*HD + r)*DSTATE + n];
    }
    if (tid < 64) sA[tid] = expf(g_acs[(c*64 + tid)*NH + h]);
    __syncthreads();

    const int i0 = (tid & 15)*4, p0 = (tid >> 4)*4;
    float acc[4][4] = {};
    for (int n = 0; n < 128; n++) {
        float cv[4], sv[4];
#pragma unroll
        for (int ii = 0; ii < 4; ii++) cv[ii] = sC[(i0+ii)*129 + n];
#pragma unroll
        for (int jj = 0; jj < 4; jj++) sv[jj] = sS[(p0+jj)*129 + n];
#pragma unroll
        for (int ii = 0; ii < 4; ii++)
#pragma unroll
            for (int jj = 0; jj < 4; jj++) acc[ii][jj] += cv[ii]*sv[jj];
    }
    float dsk = Dp[h];
#pragma unroll
    for (int ii = 0; ii < 4; ii++) {
        int l = c*64 + i0 + ii;
        float dec = sA[i0 + ii];
#pragma unroll
        for (int jj = 0; jj < 4; jj++) {
            int pp = p0 + jj;
            size_t o = (size_t)l*DIN + h*HD + pp;
            g_y[o] += acc[ii][jj]*dec + g_xBC[(size_t)l*CONVD + h*HD + pp]*dsk;
        }
    }
}

// ---------------- launch ----------------
extern "C" void kernel_launch(void* const* d_in, const int* in_sizes, int n_in,
                              void* d_out, int out_size) {
    const int*   ids  = (const int*)  d_in[0];
    const float* emb  = (const float*)d_in[1];
    const float* inw  = (const float*)d_in[2];
    const float* cw   = (const float*)d_in[3];
    const float* cb   = (const float*)d_in[4];
    const float* dtb  = (const float*)d_in[5];
    const float* alog = (const float*)d_in[6];
    const float* Dp   = (const float*)d_in[7];
    const float* mnw  = (const float*)d_in[8];
    const float* ow   = (const float*)d_in[9];
    const float* lnw  = (const float*)d_in[10];
    const float* nfw  = (const float*)d_in[11];
    float* out = (float*)d_out;

    float *px, *pu, *pzx, *pyn;
    cudaGetSymbolAddress((void**)&px,  g_x);
    cudaGetSymbolAddress((void**)&pu,  g_u);
    cudaGetSymbolAddress((void**)&pzx, g_zx);
    cudaGetSymbolAddress((void**)&pyn, g_yn);

    const int CHUNK_SMEM = (64*129*2 + 64*65*2 + 128) * (int)sizeof(float);  // 99,840 B
    const int YOFF_SMEM  = (64*129*2 + 64) * (int)sizeof(float);             // 66,304 B
    cudaFuncSetAttribute(chunk_kernel, cudaFuncAttributeMaxDynamicSharedMemorySize, CHUNK_SMEM);
    cudaFuncSetAttribute(yoff_kernel,  cudaFuncAttributeMaxDynamicSharedMemorySize, YOFF_SMEM);

    embed_kernel<<<SEQ, 256>>>(ids, emb);

    for (int i = 0; i < NL; i++) {
        rmsnorm_kernel<<<SEQ, 256>>>(px, lnw + (size_t)i*DM, pu, DM);
        gemm_kernel<<<dim3((DPROJ + 127)/128, SEQ/128), 256>>>(
            pu, inw + (size_t)i*DPROJ*DM, nullptr, pzx, SEQ, DPROJ, DM);
        conv_kernel<<<(SEQ*CONVD + 255)/256, 256>>>(cw + (size_t)i*CONVD*4, cb + (size_t)i*CONVD);
        dt_kernel<<<(SEQ*NH + 255)/256, 256>>>(dtb + i*NH, alog + i*NH);
        pack_kernel<<<SEQ*DIN/256, 256>>>();
        chunk_kernel<<<dim3(NCH, NH), 256, CHUNK_SMEM>>>();
        scan_kernel<<<NH*HD*DSTATE/256, 256>>>();
        yoff_kernel<<<dim3(NCH, NH), 256, YOFF_SMEM>>>(Dp + i*NH);
        gated_rmsnorm_kernel<<<SEQ, 256>>>(mnw + (size_t)i*DIN);
        gemm_kernel<<<dim3(DM/128, SEQ/128), 256>>>(
            pyn, ow + (size_t)i*DM*DIN, px, px, SEQ, DM, DIN);
    }

    rmsnorm_kernel<<<SEQ, 256>>>(px, nfw, pu, DM);
    gemm_kernel<<<dim3((NV + 127)/128, SEQ/128), 256>>>(
        pu, emb, nullptr, out, SEQ, NV, DM);
}

// round 3
// speedup vs baseline: 2.2173x; 2.2173x over previous
#include <cuda_runtime.h>
#include <cuda_bf16.h>
#include <math.h>
#include <stdint.h>

#define SEQ    2048
#define DM     768
#define NL     4
#define DSTATE 128
#define HD     64
#define NCH    32
#define DIN    1536
#define NH     24
#define CONVD  1792
#define DPROJ  3352
#define NV     50288

// ---------------- scratch (device globals) ----------------
__device__ __align__(128) float g_x[SEQ*DM];
__device__ __align__(128) float g_zx[SEQ*DPROJ];
__device__ __align__(128) float g_xBC[SEQ*CONVD];
__device__ __align__(128) float g_dt[SEQ*NH];
__device__ __align__(128) float g_Adt[SEQ*NH];
__device__ __align__(128) float g_acs[SEQ*NH];
__device__ __align__(128) float g_Asum[NCH*NH];
__device__ __align__(128) float g_xdt[SEQ*DIN];
__device__ __align__(128) float g_states[NCH*NH*HD*DSTATE];
__device__ __align__(128) float g_y[SEQ*DIN];

// split-bf16 operands
__device__ __align__(128) __nv_bfloat16 g_embh[NV*DM];
__device__ __align__(128) __nv_bfloat16 g_embl[NV*DM];
__device__ __align__(128) __nv_bfloat16 g_inwh[NL*DPROJ*DM];
__device__ __align__(128) __nv_bfloat16 g_inwl[NL*DPROJ*DM];
__device__ __align__(128) __nv_bfloat16 g_owh[NL*DM*DIN];
__device__ __align__(128) __nv_bfloat16 g_owl[NL*DM*DIN];
__device__ __align__(128) __nv_bfloat16 g_uh[SEQ*DM];
__device__ __align__(128) __nv_bfloat16 g_ul[SEQ*DM];
__device__ __align__(128) __nv_bfloat16 g_ynh[SEQ*DIN];
__device__ __align__(128) __nv_bfloat16 g_ynl[SEQ*DIN];

// ---------------- PTX helpers ----------------
__device__ __forceinline__ uint32_t smem_u32(const void* p) {
    uint32_t a;
    asm("{ .reg .u64 t; cvta.to.shared.u64 t, %1; cvt.u32.u64 %0, t; }" : "=r"(a) : "l"(p));
    return a;
}
__device__ __forceinline__ void cpa16(uint32_t dst, const void* src) {
    asm volatile("cp.async.cg.shared.global [%0], [%1], 16;" :: "r"(dst), "l"(src) : "memory");
}
#define CP_COMMIT() asm volatile("cp.async.commit_group;" ::: "memory")
#define CP_WAIT(n)  asm volatile("cp.async.wait_group %0;" :: "n"(n) : "memory")

__device__ __forceinline__ void ldsm4(uint32_t addr, uint32_t& r0, uint32_t& r1,
                                      uint32_t& r2, uint32_t& r3) {
    asm volatile("ldmatrix.sync.aligned.m8n8.x4.shared.b16 {%0,%1,%2,%3}, [%4];"
                 : "=r"(r0), "=r"(r1), "=r"(r2), "=r"(r3) : "r"(addr));
}
__device__ __forceinline__ void mma16816(float* d, const uint32_t* a, const uint32_t* b) {
    asm volatile(
        "mma.sync.aligned.m16n8k16.row.col.f32.bf16.bf16.f32 "
        "{%0,%1,%2,%3}, {%4,%5,%6,%7}, {%8,%9}, {%0,%1,%2,%3};"
        : "+f"(d[0]), "+f"(d[1]), "+f"(d[2]), "+f"(d[3])
        : "r"(a[0]), "r"(a[1]), "r"(a[2]), "r"(a[3]), "r"(b[0]), "r"(b[1]));
}

// ---------------- split-bf16 tensor-core GEMM (HMMA path) ----------------
// C(MxN) = [Ah+Al](MxK,row) * [Bh+Bl](NxK,row)^T (+ addsrc), fp32 out.
// tile 128x128, BK=32, 8 warps (2x4), each warp 64x32, double-buffered cp.async.
// smem rows padded to 80B -> ldmatrix conflict-free, no swizzle needed.
#define RS        80
#define A_BYTES   (128*RS)        // 10240
#define SLABB     (4*A_BYTES)     // Ah|Al|Bh|Bl = 40960
#define GEMM_SMEM (2*SLABB)       // 81920

__global__ void __launch_bounds__(256, 1)
gemm_tc(const __nv_bfloat16* __restrict__ Ah, const __nv_bfloat16* __restrict__ Al,
        const __nv_bfloat16* __restrict__ Bh, const __nv_bfloat16* __restrict__ Bl,
        const float* __restrict__ addsrc, float* __restrict__ C,
        int M, int N, int K) {
    extern __shared__ char dsm[];
    const uint32_t sbase = smem_u32(dsm);
    const int tid = threadIdx.x, wid = tid >> 5, lane = tid & 31;
    const int m0 = blockIdx.x * 128, n0 = blockIdx.y * 128;
    const int nslab = K >> 5;
    const int mw = (wid & 1) * 64, nw = (wid >> 1) * 32;

    float acc[4][4][4];
#pragma unroll
    for (int i = 0; i < 4; i++)
#pragma unroll
        for (int j = 0; j < 4; j++)
#pragma unroll
            for (int k = 0; k < 4; k++) acc[i][j][k] = 0.f;

    auto load_slab = [&](int s, int b) {
        const int k0 = s << 5;
        const uint32_t base = sbase + b * SLABB;
        // A: 128 rows x 2 chunks/thread pass (512 chunk slots)
#pragma unroll
        for (int t = 0; t < 2; t++) {
            int idx = tid + t * 256;
            int r = idx >> 2, c = idx & 3;
            uint32_t d = base + r * RS + c * 16;
            size_t g = (size_t)(m0 + r) * K + k0 + c * 8;
            cpa16(d, Ah + g);
            cpa16(d + A_BYTES, Al + g);
        }
        // B: clamp OOB rows
#pragma unroll
        for (int t = 0; t < 2; t++) {
            int idx = tid + t * 256;
            int r = idx >> 2, c = idx & 3;
            int rn = n0 + r; if (rn > N - 1) rn = N - 1;
            uint32_t d = base + 2 * A_BYTES + r * RS + c * 16;
            size_t g = (size_t)rn * K + k0 + c * 8;
            cpa16(d, Bh + g);
            cpa16(d + A_BYTES, Bl + g);
        }
    };

    load_slab(0, 0);
    CP_COMMIT();

    for (int s = 0; s < nslab; s++) {
        const int b = s & 1;
        if (s + 1 < nslab) {
            load_slab(s + 1, b ^ 1);
            CP_COMMIT();
            CP_WAIT(1);
        } else {
            CP_WAIT(0);
        }
        __syncthreads();

        const uint32_t abase = sbase + b * SLABB;
        const uint32_t bbase = abase + 2 * A_BYTES;
#pragma unroll
        for (int ks = 0; ks < 2; ks++) {
            uint32_t a_h[4][4], a_l[4][4], b_h[4][2], b_l[4][2];
#pragma unroll
            for (int mi = 0; mi < 4; mi++) {
                uint32_t ad = abase + (mw + mi * 16 + (lane & 15)) * RS
                            + ((lane >> 4) << 4) + ks * 32;
                ldsm4(ad, a_h[mi][0], a_h[mi][1], a_h[mi][2], a_h[mi][3]);
                ldsm4(ad + A_BYTES, a_l[mi][0], a_l[mi][1], a_l[mi][2], a_l[mi][3]);
            }
#pragma unroll
            for (int nb = 0; nb < 2; nb++) {
                uint32_t bd = bbase + (nw + nb * 16 + ((lane >> 4) << 3) + (lane & 7)) * RS
                            + (((lane >> 3) & 1) << 4) + ks * 32;
                uint32_t r0, r1, r2, r3;
                ldsm4(bd, r0, r1, r2, r3);
                b_h[2*nb][0] = r0; b_h[2*nb][1] = r1;
                b_h[2*nb+1][0] = r2; b_h[2*nb+1][1] = r3;
                ldsm4(bd + A_BYTES, r0, r1, r2, r3);
                b_l[2*nb][0] = r0; b_l[2*nb][1] = r1;
                b_l[2*nb+1][0] = r2; b_l[2*nb+1][1] = r3;
            }
#pragma unroll
            for (int mi = 0; mi < 4; mi++)
#pragma unroll
                for (int ni = 0; ni < 4; ni++) {
                    mma16816(acc[mi][ni], a_h[mi], b_h[ni]);
                    mma16816(acc[mi][ni], a_h[mi], b_l[ni]);
                    mma16816(acc[mi][ni], a_l[mi], b_h[ni]);
                }
        }
        __syncthreads();
    }

    // epilogue: d-frag -> float2 stores (+ optional residual add)
#pragma unroll
    for (int mi = 0; mi < 4; mi++) {
#pragma unroll
        for (int half = 0; half < 2; half++) {
            int m = m0 + mw + mi * 16 + (lane >> 2) + half * 8;
#pragma unroll
            for (int ni = 0; ni < 4; ni++) {
                int n = n0 + nw + ni * 8 + 2 * (lane & 3);
                if (n < N) {
                    float2 v = make_float2(acc[mi][ni][half*2], acc[mi][ni][half*2+1]);
                    float* p = C + (size_t)m * N + n;
                    if (addsrc) {
                        const float* q = addsrc + (size_t)m * N + n;
                        v.x += q[0]; v.y += q[1];
                    }
                    p[0] = v.x; p[1] = v.y;
                }
            }
        }
    }
}

// ---------------- misc kernels ----------------
__device__ __forceinline__ float block_sum(float v) {
    __shared__ float red[256];
    int t = threadIdx.x;
    red[t] = v; __syncthreads();
    for (int s = 128; s > 0; s >>= 1) {
        if (t < s) red[t] += red[t + s];
        __syncthreads();
    }
    float r = red[0];
    __syncthreads();
    return r;
}

__global__ void embed_kernel(const int* __restrict__ ids, const float* __restrict__ emb) {
    int l = blockIdx.x;
    int id = ids[l];
    for (int d = threadIdx.x; d < DM; d += 256)
        g_x[(size_t)l*DM + d] = emb[(size_t)id*DM + d];
}

__global__ void split_kernel(const float* __restrict__ s, __nv_bfloat16* __restrict__ h,
                             __nv_bfloat16* __restrict__ l, int n4) {
    int i = blockIdx.x*256 + threadIdx.x;
    if (i >= n4) return;
    float4 v = ((const float4*)s)[i];
    __nv_bfloat16 h0 = __float2bfloat16(v.x), h1 = __float2bfloat16(v.y);
    __nv_bfloat16 h2 = __float2bfloat16(v.z), h3 = __float2bfloat16(v.w);
    h[i*4+0] = h0; h[i*4+1] = h1; h[i*4+2] = h2; h[i*4+3] = h3;
    l[i*4+0] = __float2bfloat16(v.x - __bfloat162float(h0));
    l[i*4+1] = __float2bfloat16(v.y - __bfloat162float(h1));
    l[i*4+2] = __float2bfloat16(v.z - __bfloat162float(h2));
    l[i*4+3] = __float2bfloat16(v.w - __bfloat162float(h3));
}

__global__ void rmsnorm_split_kernel(const float* __restrict__ in, const float* __restrict__ w,
                                     __nv_bfloat16* __restrict__ oh, __nv_bfloat16* __restrict__ ol,
                                     int D) {
    int row = blockIdx.x;
    const float* x = in + (size_t)row*D;
    float s = 0.f;
    for (int i = threadIdx.x; i < D; i += 256) { float v = x[i]; s += v*v; }
    float tot = block_sum(s);
    float sc = rsqrtf(tot / (float)D + 1e-5f);
    for (int i = threadIdx.x; i < D; i += 256) {
        float v = x[i] * sc * w[i];
        __nv_bfloat16 h = __float2bfloat16(v);
        oh[(size_t)row*D + i] = h;
        ol[(size_t)row*D + i] = __float2bfloat16(v - __bfloat162float(h));
    }
}

__global__ void gated_rmsnorm_kernel(const float* __restrict__ w) {
    int row = blockIdx.x;
    __shared__ float tbuf[DIN];
    float s = 0.f;
    for (int i = threadIdx.x; i < DIN; i += 256) {
        float v = g_y[(size_t)row*DIN + i];
        float z = g_zx[(size_t)row*DPROJ + i];
        float g = v * (z / (1.f + expf(-z)));
        tbuf[i] = g; s += g*g;
    }
    float tot = block_sum(s);
    float sc = rsqrtf(tot / (float)DIN + 1e-5f);
    for (int i = threadIdx.x; i < DIN; i += 256) {
        float v = tbuf[i] * sc * w[i];
        __nv_bfloat16 h = __float2bfloat16(v);
        g_ynh[(size_t)row*DIN + i] = h;
        g_ynl[(size_t)row*DIN + i] = __float2bfloat16(v - __bfloat162float(h));
    }
}

__global__ void conv_kernel(const float* __restrict__ cw, const float* __restrict__ cb) {
    int idx = blockIdx.x*256 + threadIdx.x;
    if (idx >= SEQ*CONVD) return;
    int l = idx / CONVD, ch = idx % CONVD;
    float s = cb[ch];
#pragma unroll
    for (int k = 0; k < 4; k++) {
        int t = l - 3 + k;
        if (t >= 0) s += cw[ch*4 + k] * g_zx[(size_t)t*DPROJ + DIN + ch];
    }
    g_xBC[idx] = s / (1.f + expf(-s));
}

__global__ void dt_kernel(const float* __restrict__ dtb, const float* __restrict__ alog) {
    int idx = blockIdx.x*256 + threadIdx.x;
    if (idx >= SEQ*NH) return;
    int h = idx % NH;
    float v = g_zx[(size_t)(idx/NH)*DPROJ + DIN + CONVD + h] + dtb[h];
    float dt = (v > 20.f) ? v : log1pf(expf(v));
    g_dt[idx] = dt;
    g_Adt[idx] = -expf(alog[h]) * dt;
}

__global__ void pack_kernel() {
    int idx = blockIdx.x*256 + threadIdx.x;
    int l = idx / DIN, i = idx % DIN;
    g_xdt[idx] = g_xBC[(size_t)l*CONVD + i] * g_dt[l*NH + i/HD];
}

__global__ void __launch_bounds__(256)
chunk_kernel() {
    extern __shared__ float sm[];
    float* sB   = sm;
    float* sC   = sB + 64*129;
    float* sX   = sC + 64*129;
    float* sM   = sX + 64*65;
    float* sAcs = sM + 64*65;
    float* sDec = sAcs + 64;

    const int c = blockIdx.x, h = blockIdx.y, tid = threadIdx.x;

    for (int idx = tid; idx < 64*128; idx += 256) {
        int r = idx >> 7, n = idx & 127;
        const float* row = g_xBC + (size_t)(c*64 + r)*CONVD + DIN;
        sB[r*129 + n] = row[n];
        sC[r*129 + n] = row[DSTATE + n];
    }
    for (int idx = tid; idx < 64*64; idx += 256) {
        int r = idx >> 6, p = idx & 63;
        sX[r*65 + p] = g_xdt[(size_t)(c*64 + r)*DIN + h*HD + p];
    }
    if (tid == 0) {
        float run = 0.f;
        for (int t = 0; t < 64; t++) {
            run += g_Adt[(c*64 + t)*NH + h];
            sAcs[t] = run;
            g_acs[(c*64 + t)*NH + h] = run;
        }
        g_Asum[c*NH + h] = run;
    }
    __syncthreads();
    if (tid < 64) sDec[tid] = expf(sAcs[63] - sAcs[tid]);
    __syncthreads();

    {
        const int i0 = (tid & 15)*4, j0 = (tid >> 4)*4;
        float acc[4][4] = {};
        for (int n = 0; n < 128; n++) {
            float a[4], b[4];
#pragma unroll
            for (int ii = 0; ii < 4; ii++) a[ii] = sC[(i0+ii)*129 + n];
#pragma unroll
            for (int jj = 0; jj < 4; jj++) b[jj] = sB[(j0+jj)*129 + n];
#pragma unroll
            for (int ii = 0; ii < 4; ii++)
#pragma unroll
                for (int jj = 0; jj < 4; jj++) acc[ii][jj] += a[ii]*b[jj];
        }
#pragma unroll
        for (int ii = 0; ii < 4; ii++)
#pragma unroll
            for (int jj = 0; jj < 4; jj++) {
                int i = i0 + ii, j = j0 + jj;
                sM[i*65 + j] = (j <= i) ? acc[ii][jj]*expf(sAcs[i] - sAcs[j]) : 0.f;
            }
    }
    __syncthreads();

    {
        const int i0 = (tid & 15)*4, p0 = (tid >> 4)*4;
        float acc[4][4] = {};
        for (int j = 0; j < 64; j++) {
            float m[4], xv[4];
#pragma unroll
            for (int ii = 0; ii < 4; ii++) m[ii] = sM[(i0+ii)*65 + j];
#pragma unroll
            for (int jj = 0; jj < 4; jj++) xv[jj] = sX[j*65 + p0 + jj];
#pragma unroll
            for (int ii = 0; ii < 4; ii++)
#pragma unroll
                for (int jj = 0; jj < 4; jj++) acc[ii][jj] += m[ii]*xv[jj];
        }
#pragma unroll
        for (int ii = 0; ii < 4; ii++)
#pragma unroll
            for (int jj = 0; jj < 4; jj++)
                g_y[(size_t)(c*64 + i0 + ii)*DIN + h*HD + p0 + jj] = acc[ii][jj];
    }

    {
        const int p0 = (tid & 15)*4, n0 = (tid >> 4)*8;
        float acc[4][8] = {};
        for (int j = 0; j < 64; j++) {
            float d = sDec[j];
            float xv[4], bv[8];
#pragma unroll
            for (int ii = 0; ii < 4; ii++) xv[ii] = sX[j*65 + p0 + ii]*d;
#pragma unroll
            for (int jj = 0; jj < 8; jj++) bv[jj] = sB[j*129 + n0 + jj];
#pragma unroll
            for (int ii = 0; ii < 4; ii++)
#pragma unroll
                for (int jj = 0; jj < 8; jj++) acc[ii][jj] += xv[ii]*bv[jj];
        }
#pragma unroll
        for (int ii = 0; ii < 4; ii++)
#pragma unroll
            for (int jj = 0; jj < 8; jj++)
                g_states[(size_t)((c*NH + h)*HD + p0 + ii)*DSTATE + n0 + jj] = acc[ii][jj];
    }
}

__global__ void scan_kernel() {
    int idx = blockIdx.x*256 + threadIdx.x;
    int h = idx / (HD*DSTATE);
    int rem = idx % (HD*DSTATE);
    float S = 0.f;
    for (int c = 0; c < NCH; c++) {
        size_t off = (size_t)(c*NH + h)*HD*DSTATE + rem;
        float cur = g_states[off];
        g_states[off] = S;
        S = expf(g_Asum[c*NH + h])*S + cur;
    }
}

__global__ void __launch_bounds__(256)
yoff_kernel(const float* __restrict__ Dp) {
    extern __shared__ float sm[];
    float* sC = sm;
    float* sS = sC + 64*129;
    float* sA = sS + 64*129;
    const int c = blockIdx.x, h = blockIdx.y, tid = threadIdx.x;

    for (int idx = tid; idx < 64*128; idx += 256) {
        int r = idx >> 7, n = idx & 127;
        sC[r*129 + n] = g_xBC[(size_t)(c*64 + r)*CONVD + DIN + DSTATE + n];
        sS[r*129 + n] = g_states[(size_t)((c*NH + h)*HD + r)*DSTATE + n];
    }
    if (tid < 64) sA[tid] = expf(g_acs[(c*64 + tid)*NH + h]);
    __syncthreads();

    const int i0 = (tid & 15)*4, p0 = (tid >> 4)*4;
    float acc[4][4] = {};
    for (int n = 0; n < 128; n++) {
        float cv[4], sv[4];
#pragma unroll
        for (int ii = 0; ii < 4; ii++) cv[ii] = sC[(i0+ii)*129 + n];
#pragma unroll
        for (int jj = 0; jj < 4; jj++) sv[jj] = sS[(p0+jj)*129 + n];
#pragma unroll
        for (int ii = 0; ii < 4; ii++)
#pragma unroll
            for (int jj = 0; jj < 4; jj++) acc[ii][jj] += cv[ii]*sv[jj];
    }
    float dsk = Dp[h];
#pragma unroll
    for (int ii = 0; ii < 4; ii++) {
        int l = c*64 + i0 + ii;
        float dec = sA[i0 + ii];
#pragma unroll
        for (int jj = 0; jj < 4; jj++) {
            int pp = p0 + jj;
            size_t o = (size_t)l*DIN + h*HD + pp;
            g_y[o] += acc[ii][jj]*dec + g_xBC[(size_t)l*CONVD + h*HD + pp]*dsk;
        }
    }
}

// ---------------- launch ----------------
extern "C" void kernel_launch(void* const* d_in, const int* in_sizes, int n_in,
                              void* d_out, int out_size) {
    const int*   ids  = (const int*)  d_in[0];
    const float* emb  = (const float*)d_in[1];
    const float* inw  = (const float*)d_in[2];
    const float* cw   = (const float*)d_in[3];
    const float* cb   = (const float*)d_in[4];
    const float* dtb  = (const float*)d_in[5];
    const float* alog = (const float*)d_in[6];
    const float* Dp   = (const float*)d_in[7];
    const float* mnw  = (const float*)d_in[8];
    const float* ow   = (const float*)d_in[9];
    const float* lnw  = (const float*)d_in[10];
    const float* nfw  = (const float*)d_in[11];
    float* out = (float*)d_out;

    float *px, *pzx;
    __nv_bfloat16 *pembh, *pembl, *pinwh, *pinwl, *powh, *powl, *puh, *pul, *pynh, *pynl;
    cudaGetSymbolAddress((void**)&px,   g_x);
    cudaGetSymbolAddress((void**)&pzx,  g_zx);
    cudaGetSymbolAddress((void**)&pembh, g_embh);
    cudaGetSymbolAddress((void**)&pembl, g_embl);
    cudaGetSymbolAddress((void**)&pinwh, g_inwh);
    cudaGetSymbolAddress((void**)&pinwl, g_inwl);
    cudaGetSymbolAddress((void**)&powh,  g_owh);
    cudaGetSymbolAddress((void**)&powl,  g_owl);
    cudaGetSymbolAddress((void**)&puh,   g_uh);
    cudaGetSymbolAddress((void**)&pul,   g_ul);
    cudaGetSymbolAddress((void**)&pynh,  g_ynh);
    cudaGetSymbolAddress((void**)&pynl,  g_ynl);

    const int CHUNK_SMEM = (64*129*2 + 64*65*2 + 128) * (int)sizeof(float);
    const int YOFF_SMEM  = (64*129*2 + 64) * (int)sizeof(float);
    cudaFuncSetAttribute(chunk_kernel, cudaFuncAttributeMaxDynamicSharedMemorySize, CHUNK_SMEM);
    cudaFuncSetAttribute(yoff_kernel,  cudaFuncAttributeMaxDynamicSharedMemorySize, YOFF_SMEM);
    cudaFuncSetAttribute(gemm_tc,      cudaFuncAttributeMaxDynamicSharedMemorySize, GEMM_SMEM);

    // weight splits (fp32 -> bf16 hi/lo)
    split_kernel<<<(NV*DM/4 + 255)/256, 256>>>(emb, pembh, pembl, NV*DM/4);
    split_kernel<<<(NL*DPROJ*DM/4 + 255)/256, 256>>>(inw, pinwh, pinwl, NL*DPROJ*DM/4);
    split_kernel<<<(NL*DM*DIN/4 + 255)/256, 256>>>(ow, powh, powl, NL*DM*DIN/4);

    embed_kernel<<<SEQ, 256>>>(ids, emb);

    for (int i = 0; i < NL; i++) {
        rmsnorm_split_kernel<<<SEQ, 256>>>(px, lnw + (size_t)i*DM, puh, pul, DM);
        gemm_tc<<<dim3(SEQ/128, (DPROJ + 127)/128), 256, GEMM_SMEM>>>(
            puh, pul, pinwh + (size_t)i*DPROJ*DM, pinwl + (size_t)i*DPROJ*DM,
            nullptr, pzx, SEQ, DPROJ, DM);
        conv_kernel<<<(SEQ*CONVD + 255)/256, 256>>>(cw + (size_t)i*CONVD*4, cb + (size_t)i*CONVD);
        dt_kernel<<<(SEQ*NH + 255)/256, 256>>>(dtb + i*NH, alog + i*NH);
        pack_kernel<<<SEQ*DIN/256, 256>>>();
        chunk_kernel<<<dim3(NCH, NH), 256, CHUNK_SMEM>>>();
        scan_kernel<<<NH*HD*DSTATE/256, 256>>>();
        yoff_kernel<<<dim3(NCH, NH), 256, YOFF_SMEM>>>(Dp + i*NH);
        gated_rmsnorm_kernel<<<SEQ, 256>>>(mnw + (size_t)i*DIN);
        gemm_tc<<<dim3(SEQ/128, DM/128), 256, GEMM_SMEM>>>(
            pynh, pynl, powh + (size_t)i*DM*DIN, powl + (size_t)i*DM*DIN,
            px, px, SEQ, DM, DIN);
    }

    rmsnorm_split_kernel<<<SEQ, 256>>>(px, nfw, puh, pul, DM);
    gemm_tc<<<dim3(SEQ/128, (NV + 127)/128), 256, GEMM_SMEM>>>(
        puh, pul, pembh, pembl, nullptr, out, SEQ, NV, DM);
}

// round 4
// speedup vs baseline: 2.2750x; 1.0260x over previous
#include <cuda_runtime.h>
#include <cuda_bf16.h>
#include <math.h>
#include <stdint.h>

#define SEQ    2048
#define DM     768
#define NL     4
#define DSTATE 128
#define HD     64
#define NCH    32
#define DIN    1536
#define NH     24
#define CONVD  1792
#define DPROJ  3352
#define NV     50288

// ---------------- scratch (device globals) ----------------
__device__ __align__(128) float g_x[SEQ*DM];
__device__ __align__(128) float g_zx[SEQ*DPROJ];
__device__ __align__(128) float g_xBC[SEQ*CONVD];
__device__ __align__(128) float g_dt[SEQ*NH];
__device__ __align__(128) float g_Adt[SEQ*NH];
__device__ __align__(128) float g_acs[SEQ*NH];
__device__ __align__(128) float g_Asum[NCH*NH];
__device__ __align__(128) float g_xdt[SEQ*DIN];
__device__ __align__(128) float g_states[NCH*NH*HD*DSTATE];
__device__ __align__(128) float g_y[SEQ*DIN];

// split-bf16 operands
__device__ __align__(128) __nv_bfloat16 g_embh[NV*DM];
__device__ __align__(128) __nv_bfloat16 g_embl[NV*DM];
__device__ __align__(128) __nv_bfloat16 g_inwh[NL*DPROJ*DM];
__device__ __align__(128) __nv_bfloat16 g_inwl[NL*DPROJ*DM];
__device__ __align__(128) __nv_bfloat16 g_owh[NL*DM*DIN];
__device__ __align__(128) __nv_bfloat16 g_owl[NL*DM*DIN];
__device__ __align__(128) __nv_bfloat16 g_uh[SEQ*DM];
__device__ __align__(128) __nv_bfloat16 g_ul[SEQ*DM];
__device__ __align__(128) __nv_bfloat16 g_ynh[SEQ*DIN];
__device__ __align__(128) __nv_bfloat16 g_ynl[SEQ*DIN];

// ---------------- PTX helpers ----------------
__device__ __forceinline__ uint32_t smem_u32(const void* p) {
    uint32_t a;
    asm("{ .reg .u64 t; cvta.to.shared.u64 t, %1; cvt.u32.u64 %0, t; }" : "=r"(a) : "l"(p));
    return a;
}
__device__ __forceinline__ void cpa16(uint32_t dst, const void* src) {
    asm volatile("cp.async.cg.shared.global [%0], [%1], 16;" :: "r"(dst), "l"(src) : "memory");
}
#define CP_COMMIT() asm volatile("cp.async.commit_group;" ::: "memory")
#define CP_WAIT(n)  asm volatile("cp.async.wait_group %0;" :: "n"(n) : "memory")

__device__ __forceinline__ void ldsm4(uint32_t addr, uint32_t& r0, uint32_t& r1,
                                      uint32_t& r2, uint32_t& r3) {
    asm volatile("ldmatrix.sync.aligned.m8n8.x4.shared.b16 {%0,%1,%2,%3}, [%4];"
                 : "=r"(r0), "=r"(r1), "=r"(r2), "=r"(r3) : "r"(addr));
}
__device__ __forceinline__ void mma16816(float* d, const uint32_t* a, const uint32_t* b) {
    asm volatile(
        "mma.sync.aligned.m16n8k16.row.col.f32.bf16.bf16.f32 "
        "{%0,%1,%2,%3}, {%4,%5,%6,%7}, {%8,%9}, {%0,%1,%2,%3};"
        : "+f"(d[0]), "+f"(d[1]), "+f"(d[2]), "+f"(d[3])
        : "r"(a[0]), "r"(a[1]), "r"(a[2]), "r"(a[3]), "r"(b[0]), "r"(b[1]));
}

// ---------------- split-bf16 tensor-core GEMM (HMMA path) ----------------
// C(MxN) = [Ah+Al](MxK,row) * [Bh+Bl](NxK,row)^T (+ addsrc), fp32 out.
// tile 128x128, BK=32, 8 warps (2x4), each warp 64x32, double-buffered cp.async.
// smem rows padded to 80B -> ldmatrix conflict-free, no swizzle needed.
// MMA issue is TERM-MAJOR: 16 independent MMAs between accumulator reuse.
#define RS        80
#define A_BYTES   (128*RS)        // 10240
#define SLABB     (4*A_BYTES)     // Ah|Al|Bh|Bl = 40960
#define GEMM_SMEM (2*SLABB)       // 81920

__global__ void __launch_bounds__(256, 1)
gemm_tc(const __nv_bfloat16* __restrict__ Ah, const __nv_bfloat16* __restrict__ Al,
        const __nv_bfloat16* __restrict__ Bh, const __nv_bfloat16* __restrict__ Bl,
        const float* __restrict__ addsrc, float* __restrict__ C,
        int M, int N, int K) {
    extern __shared__ char dsm[];
    const uint32_t sbase = smem_u32(dsm);
    const int tid = threadIdx.x, wid = tid >> 5, lane = tid & 31;
    const int m0 = blockIdx.x * 128, n0 = blockIdx.y * 128;
    const int nslab = K >> 5;
    const int mw = (wid & 1) * 64, nw = (wid >> 1) * 32;

    float acc[4][4][4];
#pragma unroll
    for (int i = 0; i < 4; i++)
#pragma unroll
        for (int j = 0; j < 4; j++)
#pragma unroll
            for (int k = 0; k < 4; k++) acc[i][j][k] = 0.f;

    auto load_slab = [&](int s, int b) {
        const int k0 = s << 5;
        const uint32_t base = sbase + b * SLABB;
#pragma unroll
        for (int t = 0; t < 2; t++) {
            int idx = tid + t * 256;
            int r = idx >> 2, c = idx & 3;
            uint32_t d = base + r * RS + c * 16;
            size_t g = (size_t)(m0 + r) * K + k0 + c * 8;
            cpa16(d, Ah + g);
            cpa16(d + A_BYTES, Al + g);
        }
#pragma unroll
        for (int t = 0; t < 2; t++) {
            int idx = tid + t * 256;
            int r = idx >> 2, c = idx & 3;
            int rn = n0 + r; if (rn > N - 1) rn = N - 1;
            uint32_t d = base + 2 * A_BYTES + r * RS + c * 16;
            size_t g = (size_t)rn * K + k0 + c * 8;
            cpa16(d, Bh + g);
            cpa16(d + A_BYTES, Bl + g);
        }
    };

    load_slab(0, 0);
    CP_COMMIT();

    for (int s = 0; s < nslab; s++) {
        const int b = s & 1;
        if (s + 1 < nslab) {
            load_slab(s + 1, b ^ 1);
            CP_COMMIT();
            CP_WAIT(1);
        } else {
            CP_WAIT(0);
        }
        __syncthreads();

        const uint32_t abase = sbase + b * SLABB;
        const uint32_t bbase = abase + 2 * A_BYTES;
#pragma unroll
        for (int ks = 0; ks < 2; ks++) {
            uint32_t a_h[4][4], a_l[4][4], b_h[4][2], b_l[4][2];
#pragma unroll
            for (int mi = 0; mi < 4; mi++) {
                uint32_t ad = abase + (mw + mi * 16 + (lane & 15)) * RS
                            + ((lane >> 4) << 4) + ks * 32;
                ldsm4(ad, a_h[mi][0], a_h[mi][1], a_h[mi][2], a_h[mi][3]);
                ldsm4(ad + A_BYTES, a_l[mi][0], a_l[mi][1], a_l[mi][2], a_l[mi][3]);
            }
#pragma unroll
            for (int nb = 0; nb < 2; nb++) {
                uint32_t bd = bbase + (nw + nb * 16 + ((lane >> 4) << 3) + (lane & 7)) * RS
                            + (((lane >> 3) & 1) << 4) + ks * 32;
                uint32_t r0, r1, r2, r3;
                ldsm4(bd, r0, r1, r2, r3);
                b_h[2*nb][0] = r0; b_h[2*nb][1] = r1;
                b_h[2*nb+1][0] = r2; b_h[2*nb+1][1] = r3;
                ldsm4(bd + A_BYTES, r0, r1, r2, r3);
                b_l[2*nb][0] = r0; b_l[2*nb][1] = r1;
                b_l[2*nb+1][0] = r2; b_l[2*nb+1][1] = r3;
            }
            // TERM-MAJOR: all hh, then all hl, then all lh -> reuse distance 16
#pragma unroll
            for (int mi = 0; mi < 4; mi++)
#pragma unroll
                for (int ni = 0; ni < 4; ni++)
                    mma16816(acc[mi][ni], a_h[mi], b_h[ni]);
#pragma unroll
            for (int mi = 0; mi < 4; mi++)
#pragma unroll
                for (int ni = 0; ni < 4; ni++)
                    mma16816(acc[mi][ni], a_h[mi], b_l[ni]);
#pragma unroll
            for (int mi = 0; mi < 4; mi++)
#pragma unroll
                for (int ni = 0; ni < 4; ni++)
                    mma16816(acc[mi][ni], a_l[mi], b_h[ni]);
        }
        __syncthreads();
    }

    // epilogue: d-frag -> float2 stores (+ optional residual add)
#pragma unroll
    for (int mi = 0; mi < 4; mi++) {
#pragma unroll
        for (int half = 0; half < 2; half++) {
            int m = m0 + mw + mi * 16 + (lane >> 2) + half * 8;
#pragma unroll
            for (int ni = 0; ni < 4; ni++) {
                int n = n0 + nw + ni * 8 + 2 * (lane & 3);
                if (n < N) {
                    float2 v = make_float2(acc[mi][ni][half*2], acc[mi][ni][half*2+1]);
                    float* p = C + (size_t)m * N + n;
                    if (addsrc) {
                        const float* q = addsrc + (size_t)m * N + n;
                        v.x += q[0]; v.y += q[1];
                    }
                    p[0] = v.x; p[1] = v.y;
                }
            }
        }
    }
}

// ---------------- misc kernels ----------------
__device__ __forceinline__ float block_sum(float v) {
    __shared__ float red[256];
    int t = threadIdx.x;
    red[t] = v; __syncthreads();
    for (int s = 128; s > 0; s >>= 1) {
        if (t < s) red[t] += red[t + s];
        __syncthreads();
    }
    float r = red[0];
    __syncthreads();
    return r;
}

__global__ void embed_kernel(const int* __restrict__ ids, const float* __restrict__ emb) {
    int l = blockIdx.x;
    int id = ids[l];
    for (int d = threadIdx.x; d < DM; d += 256)
        g_x[(size_t)l*DM + d] = emb[(size_t)id*DM + d];
}

__global__ void split_kernel(const float* __restrict__ s, __nv_bfloat16* __restrict__ h,
                             __nv_bfloat16* __restrict__ l, int n4) {
    int i = blockIdx.x*256 + threadIdx.x;
    if (i >= n4) return;
    float4 v = ((const float4*)s)[i];
    __nv_bfloat16 h0 = __float2bfloat16(v.x), h1 = __float2bfloat16(v.y);
    __nv_bfloat16 h2 = __float2bfloat16(v.z), h3 = __float2bfloat16(v.w);
    h[i*4+0] = h0; h[i*4+1] = h1; h[i*4+2] = h2; h[i*4+3] = h3;
    l[i*4+0] = __float2bfloat16(v.x - __bfloat162float(h0));
    l[i*4+1] = __float2bfloat16(v.y - __bfloat162float(h1));
    l[i*4+2] = __float2bfloat16(v.z - __bfloat162float(h2));
    l[i*4+3] = __float2bfloat16(v.w - __bfloat162float(h3));
}

__global__ void rmsnorm_split_kernel(const float* __restrict__ in, const float* __restrict__ w,
                                     __nv_bfloat16* __restrict__ oh, __nv_bfloat16* __restrict__ ol,
                                     int D) {
    int row = blockIdx.x;
    const float* x = in + (size_t)row*D;
    float s = 0.f;
    for (int i = threadIdx.x; i < D; i += 256) { float v = x[i]; s += v*v; }
    float tot = block_sum(s);
    float sc = rsqrtf(tot / (float)D + 1e-5f);
    for (int i = threadIdx.x; i < D; i += 256) {
        float v = x[i] * sc * w[i];
        __nv_bfloat16 h = __float2bfloat16(v);
        oh[(size_t)row*D + i] = h;
        ol[(size_t)row*D + i] = __float2bfloat16(v - __bfloat162float(h));
    }
}

__global__ void gated_rmsnorm_kernel(const float* __restrict__ w) {
    int row = blockIdx.x;
    __shared__ float tbuf[DIN];
    float s = 0.f;
    for (int i = threadIdx.x; i < DIN; i += 256) {
        float v = g_y[(size_t)row*DIN + i];
        float z = g_zx[(size_t)row*DPROJ + i];
        float g = v * (z / (1.f + expf(-z)));
        tbuf[i] = g; s += g*g;
    }
    float tot = block_sum(s);
    float sc = rsqrtf(tot / (float)DIN + 1e-5f);
    for (int i = threadIdx.x; i < DIN; i += 256) {
        float v = tbuf[i] * sc * w[i];
        __nv_bfloat16 h = __float2bfloat16(v);
        g_ynh[(size_t)row*DIN + i] = h;
        g_ynl[(size_t)row*DIN + i] = __float2bfloat16(v - __bfloat162float(h));
    }
}

__global__ void conv_kernel(const float* __restrict__ cw, const float* __restrict__ cb) {
    int idx = blockIdx.x*256 + threadIdx.x;
    if (idx >= SEQ*CONVD) return;
    int l = idx / CONVD, ch = idx % CONVD;
    float s = cb[ch];
#pragma unroll
    for (int k = 0; k < 4; k++) {
        int t = l - 3 + k;
        if (t >= 0) s += cw[ch*4 + k] * g_zx[(size_t)t*DPROJ + DIN + ch];
    }
    g_xBC[idx] = s / (1.f + expf(-s));
}

__global__ void dt_kernel(const float* __restrict__ dtb, const float* __restrict__ alog) {
    int idx = blockIdx.x*256 + threadIdx.x;
    if (idx >= SEQ*NH) return;
    int h = idx % NH;
    float v = g_zx[(size_t)(idx/NH)*DPROJ + DIN + CONVD + h] + dtb[h];
    float dt = (v > 20.f) ? v : log1pf(expf(v));
    g_dt[idx] = dt;
    g_Adt[idx] = -expf(alog[h]) * dt;
}

__global__ void pack_kernel() {
    int idx = blockIdx.x*256 + threadIdx.x;
    int l = idx / DIN, i = idx % DIN;
    g_xdt[idx] = g_xBC[(size_t)l*CONVD + i] * g_dt[l*NH + i/HD];
}

__global__ void __launch_bounds__(256)
chunk_kernel() {
    extern __shared__ float sm[];
    float* sB   = sm;
    float* sC   = sB + 64*129;
    float* sX   = sC + 64*129;
    float* sM   = sX + 64*65;
    float* sAcs = sM + 64*65;
    float* sDec = sAcs + 64;

    const int c = blockIdx.x, h = blockIdx.y, tid = threadIdx.x;

    for (int idx = tid; idx < 64*128; idx += 256) {
        int r = idx >> 7, n = idx & 127;
        const float* row = g_xBC + (size_t)(c*64 + r)*CONVD + DIN;
        sB[r*129 + n] = row[n];
        sC[r*129 + n] = row[DSTATE + n];
    }
    for (int idx = tid; idx < 64*64; idx += 256) {
        int r = idx >> 6, p = idx & 63;
        sX[r*65 + p] = g_xdt[(size_t)(c*64 + r)*DIN + h*HD + p];
    }
    if (tid == 0) {
        float run = 0.f;
        for (int t = 0; t < 64; t++) {
            run += g_Adt[(c*64 + t)*NH + h];
            sAcs[t] = run;
            g_acs[(c*64 + t)*NH + h] = run;
        }
        g_Asum[c*NH + h] = run;
    }
    __syncthreads();
    if (tid < 64) sDec[tid] = expf(sAcs[63] - sAcs[tid]);
    __syncthreads();

    {
        const int i0 = (tid & 15)*4, j0 = (tid >> 4)*4;
        float acc[4][4] = {};
        for (int n = 0; n < 128; n++) {
            float a[4], b[4];
#pragma unroll
            for (int ii = 0; ii < 4; ii++) a[ii] = sC[(i0+ii)*129 + n];
#pragma unroll
            for (int jj = 0; jj < 4; jj++) b[jj] = sB[(j0+jj)*129 + n];
#pragma unroll
            for (int ii = 0; ii < 4; ii++)
#pragma unroll
                for (int jj = 0; jj < 4; jj++) acc[ii][jj] += a[ii]*b[jj];
        }
#pragma unroll
        for (int ii = 0; ii < 4; ii++)
#pragma unroll
            for (int jj = 0; jj < 4; jj++) {
                int i = i0 + ii, j = j0 + jj;
                sM[i*65 + j] = (j <= i) ? acc[ii][jj]*expf(sAcs[i] - sAcs[j]) : 0.f;
            }
    }
    __syncthreads();

    {
        const int i0 = (tid & 15)*4, p0 = (tid >> 4)*4;
        float acc[4][4] = {};
        for (int j = 0; j < 64; j++) {
            float m[4], xv[4];
#pragma unroll
            for (int ii = 0; ii < 4; ii++) m[ii] = sM[(i0+ii)*65 + j];
#pragma unroll
            for (int jj = 0; jj < 4; jj++) xv[jj] = sX[j*65 + p0 + jj];
#pragma unroll
            for (int ii = 0; ii < 4; ii++)
#pragma unroll
                for (int jj = 0; jj < 4; jj++) acc[ii][jj] += m[ii]*xv[jj];
        }
#pragma unroll
        for (int ii = 0; ii < 4; ii++)
#pragma unroll
            for (int jj = 0; jj < 4; jj++)
                g_y[(size_t)(c*64 + i0 + ii)*DIN + h*HD + p0 + jj] = acc[ii][jj];
    }

    {
        const int p0 = (tid & 15)*4, n0 = (tid >> 4)*8;
        float acc[4][8] = {};
        for (int j = 0; j < 64; j++) {
            float d = sDec[j];
            float xv[4], bv[8];
#pragma unroll
            for (int ii = 0; ii < 4; ii++) xv[ii] = sX[j*65 + p0 + ii]*d;
#pragma unroll
            for (int jj = 0; jj < 8; jj++) bv[jj] = sB[j*129 + n0 + jj];
#pragma unroll
            for (int ii = 0; ii < 4; ii++)
#pragma unroll
                for (int jj = 0; jj < 8; jj++) acc[ii][jj] += xv[ii]*bv[jj];
        }
#pragma unroll
        for (int ii = 0; ii < 4; ii++)
#pragma unroll
            for (int jj = 0; jj < 8; jj++)
                g_states[(size_t)((c*NH + h)*HD + p0 + ii)*DSTATE + n0 + jj] = acc[ii][jj];
    }
}

__global__ void scan_kernel() {
    int idx = blockIdx.x*256 + threadIdx.x;
    int h = idx / (HD*DSTATE);
    int rem = idx % (HD*DSTATE);
    float S = 0.f;
    for (int c = 0; c < NCH; c++) {
        size_t off = (size_t)(c*NH + h)*HD*DSTATE + rem;
        float cur = g_states[off];
        g_states[off] = S;
        S = expf(g_Asum[c*NH + h])*S + cur;
    }
}

__global__ void __launch_bounds__(256)
yoff_kernel(const float* __restrict__ Dp) {
    extern __shared__ float sm[];
    float* sC = sm;
    float* sS = sC + 64*129;
    float* sA = sS + 64*129;
    const int c = blockIdx.x, h = blockIdx.y, tid = threadIdx.x;

    for (int idx = tid; idx < 64*128; idx += 256) {
        int r = idx >> 7, n = idx & 127;
        sC[r*129 + n] = g_xBC[(size_t)(c*64 + r)*CONVD + DIN + DSTATE + n];
        sS[r*129 + n] = g_states[(size_t)((c*NH + h)*HD + r)*DSTATE + n];
    }
    if (tid < 64) sA[tid] = expf(g_acs[(c*64 + tid)*NH + h]);
    __syncthreads();

    const int i0 = (tid & 15)*4, p0 = (tid >> 4)*4;
    float acc[4][4] = {};
    for (int n = 0; n < 128; n++) {
        float cv[4], sv[4];
#pragma unroll
        for (int ii = 0; ii < 4; ii++) cv[ii] = sC[(i0+ii)*129 + n];
#pragma unroll
        for (int jj = 0; jj < 4; jj++) sv[jj] = sS[(p0+jj)*129 + n];
#pragma unroll
        for (int ii = 0; ii < 4; ii++)
#pragma unroll
            for (int jj = 0; jj < 4; jj++) acc[ii][jj] += cv[ii]*sv[jj];
    }
    float dsk = Dp[h];
#pragma unroll
    for (int ii = 0; ii < 4; ii++) {
        int l = c*64 + i0 + ii;
        float dec = sA[i0 + ii];
#pragma unroll
        for (int jj = 0; jj < 4; jj++) {
            int pp = p0 + jj;
            size_t o = (size_t)l*DIN + h*HD + pp;
            g_y[o] += acc[ii][jj]*dec + g_xBC[(size_t)l*CONVD + h*HD + pp]*dsk;
        }
    }
}

// ---------------- launch ----------------
extern "C" void kernel_launch(void* const* d_in, const int* in_sizes, int n_in,
                              void* d_out, int out_size) {
    const int*   ids  = (const int*)  d_in[0];
    const float* emb  = (const float*)d_in[1];
    const float* inw  = (const float*)d_in[2];
    const float* cw   = (const float*)d_in[3];
    const float* cb   = (const float*)d_in[4];
    const float* dtb  = (const float*)d_in[5];
    const float* alog = (const float*)d_in[6];
    const float* Dp   = (const float*)d_in[7];
    const float* mnw  = (const float*)d_in[8];
    const float* ow   = (const float*)d_in[9];
    const float* lnw  = (const float*)d_in[10];
    const float* nfw  = (const float*)d_in[11];
    float* out = (float*)d_out;

    float *px, *pzx;
    __nv_bfloat16 *pembh, *pembl, *pinwh, *pinwl, *powh, *powl, *puh, *pul, *pynh, *pynl;
    cudaGetSymbolAddress((void**)&px,   g_x);
    cudaGetSymbolAddress((void**)&pzx,  g_zx);
    cudaGetSymbolAddress((void**)&pembh, g_embh);
    cudaGetSymbolAddress((void**)&pembl, g_embl);
    cudaGetSymbolAddress((void**)&pinwh, g_inwh);
    cudaGetSymbolAddress((void**)&pinwl, g_inwl);
    cudaGetSymbolAddress((void**)&powh,  g_owh);
    cudaGetSymbolAddress((void**)&powl,  g_owl);
    cudaGetSymbolAddress((void**)&puh,   g_uh);
    cudaGetSymbolAddress((void**)&pul,   g_ul);
    cudaGetSymbolAddress((void**)&pynh,  g_ynh);
    cudaGetSymbolAddress((void**)&pynl,  g_ynl);

    const int CHUNK_SMEM = (64*129*2 + 64*65*2 + 128) * (int)sizeof(float);
    const int YOFF_SMEM  = (64*129*2 + 64) * (int)sizeof(float);
    cudaFuncSetAttribute(chunk_kernel, cudaFuncAttributeMaxDynamicSharedMemorySize, CHUNK_SMEM);
    cudaFuncSetAttribute(yoff_kernel,  cudaFuncAttributeMaxDynamicSharedMemorySize, YOFF_SMEM);
    cudaFuncSetAttribute(gemm_tc,      cudaFuncAttributeMaxDynamicSharedMemorySize, GEMM_SMEM);

    // weight splits (fp32 -> bf16 hi/lo)
    split_kernel<<<(NV*DM/4 + 255)/256, 256>>>(emb, pembh, pembl, NV*DM/4);
    split_kernel<<<(NL*DPROJ*DM/4 + 255)/256, 256>>>(inw, pinwh, pinwl, NL*DPROJ*DM/4);
    split_kernel<<<(NL*DM*DIN/4 + 255)/256, 256>>>(ow, powh, powl, NL*DM*DIN/4);

    embed_kernel<<<SEQ, 256>>>(ids, emb);

    for (int i = 0; i < NL; i++) {
        rmsnorm_split_kernel<<<SEQ, 256>>>(px, lnw + (size_t)i*DM, puh, pul, DM);
        gemm_tc<<<dim3(SEQ/128, (DPROJ + 127)/128), 256, GEMM_SMEM>>>(
            puh, pul, pinwh + (size_t)i*DPROJ*DM, pinwl + (size_t)i*DPROJ*DM,
            nullptr, pzx, SEQ, DPROJ, DM);
        conv_kernel<<<(SEQ*CONVD + 255)/256, 256>>>(cw + (size_t)i*CONVD*4, cb + (size_t)i*CONVD);
        dt_kernel<<<(SEQ*NH + 255)/256, 256>>>(dtb + i*NH, alog + i*NH);
        pack_kernel<<<SEQ*DIN/256, 256>>>();
        chunk_kernel<<<dim3(NCH, NH), 256, CHUNK_SMEM>>>();
        scan_kernel<<<NH*HD*DSTATE/256, 256>>>();
        yoff_kernel<<<dim3(NCH, NH), 256, YOFF_SMEM>>>(Dp + i*NH);
        gated_rmsnorm_kernel<<<SEQ, 256>>>(mnw + (size_t)i*DIN);
        gemm_tc<<<dim3(SEQ/128, DM/128), 256, GEMM_SMEM>>>(
            pynh, pynl, powh + (size_t)i*DM*DIN, powl + (size_t)i*DM*DIN,
            px, px, SEQ, DM, DIN);
    }

    rmsnorm_split_kernel<<<SEQ, 256>>>(px, nfw, puh, pul, DM);
    gemm_tc<<<dim3(SEQ/128, (NV + 127)/128), 256, GEMM_SMEM>>>(
        puh, pul, pembh, pembl, nullptr, out, SEQ, NV, DM);
}

// round 5
// speedup vs baseline: 3.2426x; 1.4253x over previous
#include <cuda_runtime.h>
#include <cuda_bf16.h>
#include <cuda_fp16.h>
#include <math.h>
#include <stdint.h>

#define SEQ    2048
#define DM     768
#define NL     4
#define DSTATE 128
#define HD     64
#define NCH    32
#define DIN    1536
#define NH     24
#define CONVD  1792
#define DPROJ  3352
#define NV     50288

// ---------------- scratch (device globals) ----------------
__device__ __align__(128) float g_x[SEQ*DM];
__device__ __align__(128) float g_zx[SEQ*DPROJ];
__device__ __align__(128) float g_xBC[SEQ*CONVD];
__device__ __align__(128) float g_dt[SEQ*NH];
__device__ __align__(128) float g_Adt[SEQ*NH];
__device__ __align__(128) float g_acs[SEQ*NH];
__device__ __align__(128) float g_Asum[NCH*NH];
__device__ __align__(128) float g_states[NCH*NH*HD*DSTATE];
__device__ __align__(128) float g_y[SEQ*DIN];

// split-bf16 operands (layer GEMMs)
__device__ __align__(128) __nv_bfloat16 g_inwh[NL*DPROJ*DM];
__device__ __align__(128) __nv_bfloat16 g_inwl[NL*DPROJ*DM];
__device__ __align__(128) __nv_bfloat16 g_owh[NL*DM*DIN];
__device__ __align__(128) __nv_bfloat16 g_owl[NL*DM*DIN];
__device__ __align__(128) __nv_bfloat16 g_uh[SEQ*DM];
__device__ __align__(128) __nv_bfloat16 g_ul[SEQ*DM];
__device__ __align__(128) __nv_bfloat16 g_ynh[SEQ*DIN];
__device__ __align__(128) __nv_bfloat16 g_ynl[SEQ*DIN];

// fp16 operands (logits GEMM)
__device__ __align__(128) __half g_embhalf[NV*DM];
__device__ __align__(128) __half g_uhalf[SEQ*DM];

// ---------------- PTX helpers ----------------
__device__ __forceinline__ uint32_t smem_u32(const void* p) {
    uint32_t a;
    asm("{ .reg .u64 t; cvta.to.shared.u64 t, %1; cvt.u32.u64 %0, t; }" : "=r"(a) : "l"(p));
    return a;
}
__device__ __forceinline__ void cpa16(uint32_t dst, const void* src) {
    asm volatile("cp.async.cg.shared.global [%0], [%1], 16;" :: "r"(dst), "l"(src) : "memory");
}
#define CP_COMMIT() asm volatile("cp.async.commit_group;" ::: "memory")
#define CP_WAIT(n)  asm volatile("cp.async.wait_group %0;" :: "n"(n) : "memory")

__device__ __forceinline__ void ldsm4(uint32_t addr, uint32_t& r0, uint32_t& r1,
                                      uint32_t& r2, uint32_t& r3) {
    asm volatile("ldmatrix.sync.aligned.m8n8.x4.shared.b16 {%0,%1,%2,%3}, [%4];"
                 : "=r"(r0), "=r"(r1), "=r"(r2), "=r"(r3) : "r"(addr));
}
__device__ __forceinline__ void mma_bf16(float* d, const uint32_t* a, const uint32_t* b) {
    asm volatile(
        "mma.sync.aligned.m16n8k16.row.col.f32.bf16.bf16.f32 "
        "{%0,%1,%2,%3}, {%4,%5,%6,%7}, {%8,%9}, {%0,%1,%2,%3};"
        : "+f"(d[0]), "+f"(d[1]), "+f"(d[2]), "+f"(d[3])
        : "r"(a[0]), "r"(a[1]), "r"(a[2]), "r"(a[3]), "r"(b[0]), "r"(b[1]));
}
__device__ __forceinline__ void mma_f16(float* d, const uint32_t* a, const uint32_t* b) {
    asm volatile(
        "mma.sync.aligned.m16n8k16.row.col.f32.f16.f16.f32 "
        "{%0,%1,%2,%3}, {%4,%5,%6,%7}, {%8,%9}, {%0,%1,%2,%3};"
        : "+f"(d[0]), "+f"(d[1]), "+f"(d[2]), "+f"(d[3])
        : "r"(a[0]), "r"(a[1]), "r"(a[2]), "r"(a[3]), "r"(b[0]), "r"(b[1]));
}

// ================= split-bf16 3-term GEMM (layer GEMMs) =================
// C(MxN) = [Ah+Al](MxK,row) * [Bh+Bl](NxK,row)^T (+ addsrc), fp32 out.
// tile 128x128, BK=32, 8 warps (2x4), double-buffered cp.async, RS=80 pad.
#define RS        80
#define A_BYTES   (128*RS)        // 10240
#define SLABB     (4*A_BYTES)     // 40960
#define GEMM_SMEM (2*SLABB)       // 81920

__global__ void __launch_bounds__(256, 1)
gemm_tc(const __nv_bfloat16* __restrict__ Ah, const __nv_bfloat16* __restrict__ Al,
        const __nv_bfloat16* __restrict__ Bh, const __nv_bfloat16* __restrict__ Bl,
        const float* __restrict__ addsrc, float* __restrict__ C,
        int M, int N, int K) {
    extern __shared__ char dsm[];
    const uint32_t sbase = smem_u32(dsm);
    const int tid = threadIdx.x, wid = tid >> 5, lane = tid & 31;
    const int m0 = blockIdx.x * 128, n0 = blockIdx.y * 128;
    const int nslab = K >> 5;
    const int mw = (wid & 1) * 64, nw = (wid >> 1) * 32;

    float acc[4][4][4];
#pragma unroll
    for (int i = 0; i < 4; i++)
#pragma unroll
        for (int j = 0; j < 4; j++)
#pragma unroll
            for (int k = 0; k < 4; k++) acc[i][j][k] = 0.f;

    auto load_slab = [&](int s, int b) {
        const int k0 = s << 5;
        const uint32_t base = sbase + b * SLABB;
#pragma unroll
        for (int t = 0; t < 2; t++) {
            int idx = tid + t * 256;
            int r = idx >> 2, c = idx & 3;
            uint32_t d = base + r * RS + c * 16;
            size_t g = (size_t)(m0 + r) * K + k0 + c * 8;
            cpa16(d, Ah + g);
            cpa16(d + A_BYTES, Al + g);
        }
#pragma unroll
        for (int t = 0; t < 2; t++) {
            int idx = tid + t * 256;
            int r = idx >> 2, c = idx & 3;
            int rn = n0 + r; if (rn > N - 1) rn = N - 1;
            uint32_t d = base + 2 * A_BYTES + r * RS + c * 16;
            size_t g = (size_t)rn * K + k0 + c * 8;
            cpa16(d, Bh + g);
            cpa16(d + A_BYTES, Bl + g);
        }
    };

    load_slab(0, 0);
    CP_COMMIT();

    for (int s = 0; s < nslab; s++) {
        const int b = s & 1;
        if (s + 1 < nslab) {
            load_slab(s + 1, b ^ 1);
            CP_COMMIT();
            CP_WAIT(1);
        } else {
            CP_WAIT(0);
        }
        __syncthreads();

        const uint32_t abase = sbase + b * SLABB;
        const uint32_t bbase = abase + 2 * A_BYTES;
#pragma unroll
        for (int ks = 0; ks < 2; ks++) {
            uint32_t a_h[4][4], a_l[4][4], b_h[4][2], b_l[4][2];
#pragma unroll
            for (int mi = 0; mi < 4; mi++) {
                uint32_t ad = abase + (mw + mi * 16 + (lane & 15)) * RS
                            + ((lane >> 4) << 4) + ks * 32;
                ldsm4(ad, a_h[mi][0], a_h[mi][1], a_h[mi][2], a_h[mi][3]);
                ldsm4(ad + A_BYTES, a_l[mi][0], a_l[mi][1], a_l[mi][2], a_l[mi][3]);
            }
#pragma unroll
            for (int nb = 0; nb < 2; nb++) {
                uint32_t bd = bbase + (nw + nb * 16 + ((lane >> 4) << 3) + (lane & 7)) * RS
                            + (((lane >> 3) & 1) << 4) + ks * 32;
                uint32_t r0, r1, r2, r3;
                ldsm4(bd, r0, r1, r2, r3);
                b_h[2*nb][0] = r0; b_h[2*nb][1] = r1;
                b_h[2*nb+1][0] = r2; b_h[2*nb+1][1] = r3;
                ldsm4(bd + A_BYTES, r0, r1, r2, r3);
                b_l[2*nb][0] = r0; b_l[2*nb][1] = r1;
                b_l[2*nb+1][0] = r2; b_l[2*nb+1][1] = r3;
            }
#pragma unroll
            for (int mi = 0; mi < 4; mi++)
#pragma unroll
                for (int ni = 0; ni < 4; ni++)
                    mma_bf16(acc[mi][ni], a_h[mi], b_h[ni]);
#pragma unroll
            for (int mi = 0; mi < 4; mi++)
#pragma unroll
                for (int ni = 0; ni < 4; ni++)
                    mma_bf16(acc[mi][ni], a_h[mi], b_l[ni]);
#pragma unroll
            for (int mi = 0; mi < 4; mi++)
#pragma unroll
                for (int ni = 0; ni < 4; ni++)
                    mma_bf16(acc[mi][ni], a_l[mi], b_h[ni]);
        }
        __syncthreads();
    }

#pragma unroll
    for (int mi = 0; mi < 4; mi++) {
#pragma unroll
        for (int half = 0; half < 2; half++) {
            int m = m0 + mw + mi * 16 + (lane >> 2) + half * 8;
#pragma unroll
            for (int ni = 0; ni < 4; ni++) {
                int n = n0 + nw + ni * 8 + 2 * (lane & 3);
                if (n < N) {
                    float2 v = make_float2(acc[mi][ni][half*2], acc[mi][ni][half*2+1]);
                    float* p = C + (size_t)m * N + n;
                    if (addsrc) {
                        const float* q = addsrc + (size_t)m * N + n;
                        v.x += q[0]; v.y += q[1];
                    }
                    p[0] = v.x; p[1] = v.y;
                }
            }
        }
    }
}

// ================= fp16 single-term GEMM (logits) =================
// C(MxN) = A(fp16, MxK,row) * B(fp16, NxK,row)^T, fp32 out.
#define SLABH      (2*A_BYTES)    // 20480: A | B
#define GEMMH_SMEM (2*SLABH)      // 40960

__global__ void __launch_bounds__(256, 2)
gemm_half(const __half* __restrict__ A, const __half* __restrict__ B,
          float* __restrict__ C, int M, int N, int K) {
    extern __shared__ char dsm[];
    const uint32_t sbase = smem_u32(dsm);
    const int tid = threadIdx.x, wid = tid >> 5, lane = tid & 31;
    const int m0 = blockIdx.x * 128, n0 = blockIdx.y * 128;
    const int nslab = K >> 5;
    const int mw = (wid & 1) * 64, nw = (wid >> 1) * 32;

    float acc[4][4][4];
#pragma unroll
    for (int i = 0; i < 4; i++)
#pragma unroll
        for (int j = 0; j < 4; j++)
#pragma unroll
            for (int k = 0; k < 4; k++) acc[i][j][k] = 0.f;

    auto load_slab = [&](int s, int b) {
        const int k0 = s << 5;
        const uint32_t base = sbase + b * SLABH;
        // A: 128 rows x 64B = 512 chunks of 16B; B same.
#pragma unroll
        for (int t = 0; t < 2; t++) {
            int idx = tid + t * 256;
            int r = idx >> 2, c = idx & 3;
            uint32_t d = base + r * RS + c * 16;
            cpa16(d, A + (size_t)(m0 + r) * K + k0 + c * 8);
            int rn = n0 + r; if (rn > N - 1) rn = N - 1;
            cpa16(d + A_BYTES, B + (size_t)rn * K + k0 + c * 8);
        }
    };

    load_slab(0, 0);
    CP_COMMIT();

    for (int s = 0; s < nslab; s++) {
        const int b = s & 1;
        if (s + 1 < nslab) {
            load_slab(s + 1, b ^ 1);
            CP_COMMIT();
            CP_WAIT(1);
        } else {
            CP_WAIT(0);
        }
        __syncthreads();

        const uint32_t abase = sbase + b * SLABH;
        const uint32_t bbase = abase + A_BYTES;
#pragma unroll
        for (int ks = 0; ks < 2; ks++) {
            uint32_t a_f[4][4], b_f[4][2];
#pragma unroll
            for (int mi = 0; mi < 4; mi++) {
                uint32_t ad = abase + (mw + mi * 16 + (lane & 15)) * RS
                            + ((lane >> 4) << 4) + ks * 32;
                ldsm4(ad, a_f[mi][0], a_f[mi][1], a_f[mi][2], a_f[mi][3]);
            }
#pragma unroll
            for (int nb = 0; nb < 2; nb++) {
                uint32_t bd = bbase + (nw + nb * 16 + ((lane >> 4) << 3) + (lane & 7)) * RS
                            + (((lane >> 3) & 1) << 4) + ks * 32;
                uint32_t r0, r1, r2, r3;
                ldsm4(bd, r0, r1, r2, r3);
                b_f[2*nb][0] = r0; b_f[2*nb][1] = r1;
                b_f[2*nb+1][0] = r2; b_f[2*nb+1][1] = r3;
            }
#pragma unroll
            for (int mi = 0; mi < 4; mi++)
#pragma unroll
                for (int ni = 0; ni < 4; ni++)
                    mma_f16(acc[mi][ni], a_f[mi], b_f[ni]);
        }
        __syncthreads();
    }

#pragma unroll
    for (int mi = 0; mi < 4; mi++) {
#pragma unroll
        for (int half = 0; half < 2; half++) {
            int m = m0 + mw + mi * 16 + (lane >> 2) + half * 8;
#pragma unroll
            for (int ni = 0; ni < 4; ni++) {
                int n = n0 + nw + ni * 8 + 2 * (lane & 3);
                if (n < N) {
                    float* p = C + (size_t)m * N + n;
                    p[0] = acc[mi][ni][half*2];
                    p[1] = acc[mi][ni][half*2+1];
                }
            }
        }
    }
}

// ---------------- misc kernels ----------------
__device__ __forceinline__ float block_sum(float v) {
    __shared__ float red[256];
    int t = threadIdx.x;
    red[t] = v; __syncthreads();
    for (int s = 128; s > 0; s >>= 1) {
        if (t < s) red[t] += red[t + s];
        __syncthreads();
    }
    float r = red[0];
    __syncthreads();
    return r;
}

__global__ void embed_kernel(const int* __restrict__ ids, const float* __restrict__ emb) {
    int l = blockIdx.x;
    int id = ids[l];
    for (int d = threadIdx.x; d < DM; d += 256)
        g_x[(size_t)l*DM + d] = emb[(size_t)id*DM + d];
}

__global__ void split_kernel(const float* __restrict__ s, __nv_bfloat16* __restrict__ h,
                             __nv_bfloat16* __restrict__ l, int n4) {
    int i = blockIdx.x*256 + threadIdx.x;
    if (i >= n4) return;
    float4 v = ((const float4*)s)[i];
    __nv_bfloat16 h0 = __float2bfloat16(v.x), h1 = __float2bfloat16(v.y);
    __nv_bfloat16 h2 = __float2bfloat16(v.z), h3 = __float2bfloat16(v.w);
    h[i*4+0] = h0; h[i*4+1] = h1; h[i*4+2] = h2; h[i*4+3] = h3;
    l[i*4+0] = __float2bfloat16(v.x - __bfloat162float(h0));
    l[i*4+1] = __float2bfloat16(v.y - __bfloat162float(h1));
    l[i*4+2] = __float2bfloat16(v.z - __bfloat162float(h2));
    l[i*4+3] = __float2bfloat16(v.w - __bfloat162float(h3));
}

__global__ void convert_half_kernel(const float* __restrict__ s, __half* __restrict__ d, int n4) {
    int i = blockIdx.x*256 + threadIdx.x;
    if (i >= n4) return;
    float4 v = ((const float4*)s)[i];
    __half2 a = __floats2half2_rn(v.x, v.y);
    __half2 b = __floats2half2_rn(v.z, v.w);
    ((__half2*)d)[i*2] = a;
    ((__half2*)d)[i*2+1] = b;
}

__global__ void rmsnorm_split_kernel(const float* __restrict__ in, const float* __restrict__ w,
                                     __nv_bfloat16* __restrict__ oh, __nv_bfloat16* __restrict__ ol,
                                     int D) {
    int row = blockIdx.x;
    const float* x = in + (size_t)row*D;
    float s = 0.f;
    for (int i = threadIdx.x; i < D; i += 256) { float v = x[i]; s += v*v; }
    float tot = block_sum(s);
    float sc = rsqrtf(tot / (float)D + 1e-5f);
    for (int i = threadIdx.x; i < D; i += 256) {
        float v = x[i] * sc * w[i];
        __nv_bfloat16 h = __float2bfloat16(v);
        oh[(size_t)row*D + i] = h;
        ol[(size_t)row*D + i] = __float2bfloat16(v - __bfloat162float(h));
    }
}

__global__ void rmsnorm_half_kernel(const float* __restrict__ in, const float* __restrict__ w,
                                    __half* __restrict__ out, int D) {
    int row = blockIdx.x;
    const float* x = in + (size_t)row*D;
    float s = 0.f;
    for (int i = threadIdx.x; i < D; i += 256) { float v = x[i]; s += v*v; }
    float tot = block_sum(s);
    float sc = rsqrtf(tot / (float)D + 1e-5f);
    for (int i = threadIdx.x; i < D; i += 256)
        out[(size_t)row*D + i] = __float2half(x[i] * sc * w[i]);
}

__global__ void gated_rmsnorm_kernel(const float* __restrict__ w) {
    int row = blockIdx.x;
    __shared__ float tbuf[DIN];
    float s = 0.f;
    for (int i = threadIdx.x; i < DIN; i += 256) {
        float v = g_y[(size_t)row*DIN + i];
        float z = g_zx[(size_t)row*DPROJ + i];
        float g = v * (z / (1.f + expf(-z)));
        tbuf[i] = g; s += g*g;
    }
    float tot = block_sum(s);
    float sc = rsqrtf(tot / (float)DIN + 1e-5f);
    for (int i = threadIdx.x; i < DIN; i += 256) {
        float v = tbuf[i] * sc * w[i];
        __nv_bfloat16 h = __float2bfloat16(v);
        g_ynh[(size_t)row*DIN + i] = h;
        g_ynl[(size_t)row*DIN + i] = __float2bfloat16(v - __bfloat162float(h));
    }
}

__global__ void conv_kernel(const float* __restrict__ cw, const float* __restrict__ cb) {
    int idx = blockIdx.x*256 + threadIdx.x;
    if (idx >= SEQ*CONVD) return;
    int l = idx / CONVD, ch = idx % CONVD;
    float s = cb[ch];
#pragma unroll
    for (int k = 0; k < 4; k++) {
        int t = l - 3 + k;
        if (t >= 0) s += cw[ch*4 + k] * g_zx[(size_t)t*DPROJ + DIN + ch];
    }
    g_xBC[idx] = s / (1.f + expf(-s));
}

__global__ void dt_kernel(const float* __restrict__ dtb, const float* __restrict__ alog) {
    int idx = blockIdx.x*256 + threadIdx.x;
    if (idx >= SEQ*NH) return;
    int h = idx % NH;
    float v = g_zx[(size_t)(idx/NH)*DPROJ + DIN + CONVD + h] + dtb[h];
    float dt = (v > 20.f) ? v : log1pf(expf(v));
    g_dt[idx] = dt;
    g_Adt[idx] = -expf(alog[h]) * dt;
}

__global__ void __launch_bounds__(256)
chunk_kernel() {
    extern __shared__ float sm[];
    float* sB   = sm;
    float* sC   = sB + 64*129;
    float* sX   = sC + 64*129;
    float* sM   = sX + 64*65;
    float* sAcs = sM + 64*65;
    float* sDec = sAcs + 64;

    const int c = blockIdx.x, h = blockIdx.y, tid = threadIdx.x;

    for (int idx = tid; idx < 64*128; idx += 256) {
        int r = idx >> 7, n = idx & 127;
        const float* row = g_xBC + (size_t)(c*64 + r)*CONVD + DIN;
        sB[r*129 + n] = row[n];
        sC[r*129 + n] = row[DSTATE + n];
    }
    // fused pack: X = xBC_head * dt
    for (int idx = tid; idx < 64*64; idx += 256) {
        int r = idx >> 6, p = idx & 63;
        sX[r*65 + p] = g_xBC[(size_t)(c*64 + r)*CONVD + h*HD + p] * g_dt[(c*64 + r)*NH + h];
    }
    if (tid == 0) {
        float run = 0.f;
        for (int t = 0; t < 64; t++) {
            run += g_Adt[(c*64 + t)*NH + h];
            sAcs[t] = run;
            g_acs[(c*64 + t)*NH + h] = run;
        }
        g_Asum[c*NH + h] = run;
    }
    __syncthreads();
    if (tid < 64) sDec[tid] = expf(sAcs[63] - sAcs[tid]);
    __syncthreads();

    {
        const int i0 = (tid & 15)*4, j0 = (tid >> 4)*4;
        float acc[4][4] = {};
        for (int n = 0; n < 128; n++) {
            float a[4], b[4];
#pragma unroll
            for (int ii = 0; ii < 4; ii++) a[ii] = sC[(i0+ii)*129 + n];
#pragma unroll
            for (int jj = 0; jj < 4; jj++) b[jj] = sB[(j0+jj)*129 + n];
#pragma unroll
            for (int ii = 0; ii < 4; ii++)
#pragma unroll
                for (int jj = 0; jj < 4; jj++) acc[ii][jj] += a[ii]*b[jj];
        }
#pragma unroll
        for (int ii = 0; ii < 4; ii++)
#pragma unroll
            for (int jj = 0; jj < 4; jj++) {
                int i = i0 + ii, j = j0 + jj;
                sM[i*65 + j] = (j <= i) ? acc[ii][jj]*expf(sAcs[i] - sAcs[j]) : 0.f;
            }
    }
    __syncthreads();

    {
        const int i0 = (tid & 15)*4, p0 = (tid >> 4)*4;
        float acc[4][4] = {};
        for (int j = 0; j < 64; j++) {
            float m[4], xv[4];
#pragma unroll
            for (int ii = 0; ii < 4; ii++) m[ii] = sM[(i0+ii)*65 + j];
#pragma unroll
            for (int jj = 0; jj < 4; jj++) xv[jj] = sX[j*65 + p0 + jj];
#pragma unroll
            for (int ii = 0; ii < 4; ii++)
#pragma unroll
                for (int jj = 0; jj < 4; jj++) acc[ii][jj] += m[ii]*xv[jj];
        }
#pragma unroll
        for (int ii = 0; ii < 4; ii++)
#pragma unroll
            for (int jj = 0; jj < 4; jj++)
                g_y[(size_t)(c*64 + i0 + ii)*DIN + h*HD + p0 + jj] = acc[ii][jj];
    }

    {
        const int p0 = (tid & 15)*4, n0 = (tid >> 4)*8;
        float acc[4][8] = {};
        for (int j = 0; j < 64; j++) {
            float d = sDec[j];
            float xv[4], bv[8];
#pragma unroll
            for (int ii = 0; ii < 4; ii++) xv[ii] = sX[j*65 + p0 + ii]*d;
#pragma unroll
            for (int jj = 0; jj < 8; jj++) bv[jj] = sB[j*129 + n0 + jj];
#pragma unroll
            for (int ii = 0; ii < 4; ii++)
#pragma unroll
                for (int jj = 0; jj < 8; jj++) acc[ii][jj] += xv[ii]*bv[jj];
        }
#pragma unroll
        for (int ii = 0; ii < 4; ii++)
#pragma unroll
            for (int jj = 0; jj < 8; jj++)
                g_states[(size_t)((c*NH + h)*HD + p0 + ii)*DSTATE + n0 + jj] = acc[ii][jj];
    }
}

__global__ void scan_kernel() {
    int idx = blockIdx.x*256 + threadIdx.x;
    int h = idx / (HD*DSTATE);
    int rem = idx % (HD*DSTATE);
    float S = 0.f;
    for (int c = 0; c < NCH; c++) {
        size_t off = (size_t)(c*NH + h)*HD*DSTATE + rem;
        float cur = g_states[off];
        g_states[off] = S;
        S = expf(g_Asum[c*NH + h])*S + cur;
    }
}

__global__ void __launch_bounds__(256)
yoff_kernel(const float* __restrict__ Dp) {
    extern __shared__ float sm[];
    float* sC = sm;
    float* sS = sC + 64*129;
    float* sA = sS + 64*129;
    const int c = blockIdx.x, h = blockIdx.y, tid = threadIdx.x;

    for (int idx = tid; idx < 64*128; idx += 256) {
        int r = idx >> 7, n = idx & 127;
        sC[r*129 + n] = g_xBC[(size_t)(c*64 + r)*CONVD + DIN + DSTATE + n];
        sS[r*129 + n] = g_states[(size_t)((c*NH + h)*HD + r)*DSTATE + n];
    }
    if (tid < 64) sA[tid] = expf(g_acs[(c*64 + tid)*NH + h]);
    __syncthreads();

    const int i0 = (tid & 15)*4, p0 = (tid >> 4)*4;
    float acc[4][4] = {};
    for (int n = 0; n < 128; n++) {
        float cv[4], sv[4];
#pragma unroll
        for (int ii = 0; ii < 4; ii++) cv[ii] = sC[(i0+ii)*129 + n];
#pragma unroll
        for (int jj = 0; jj < 4; jj++) sv[jj] = sS[(p0+jj)*129 + n];
#pragma unroll
        for (int ii = 0; ii < 4; ii++)
#pragma unroll
            for (int jj = 0; jj < 4; jj++) acc[ii][jj] += cv[ii]*sv[jj];
    }
    float dsk = Dp[h];
#pragma unroll
    for (int ii = 0; ii < 4; ii++) {
        int l = c*64 + i0 + ii;
        float dec = sA[i0 + ii];
#pragma unroll
        for (int jj = 0; jj < 4; jj++) {
            int pp = p0 + jj;
            size_t o = (size_t)l*DIN + h*HD + pp;
            g_y[o] += acc[ii][jj]*dec + g_xBC[(size_t)l*CONVD + h*HD + pp]*dsk;
        }
    }
}

// ---------------- launch ----------------
extern "C" void kernel_launch(void* const* d_in, const int* in_sizes, int n_in,
                              void* d_out, int out_size) {
    const int*   ids  = (const int*)  d_in[0];
    const float* emb  = (const float*)d_in[1];
    const float* inw  = (const float*)d_in[2];
    const float* cw   = (const float*)d_in[3];
    const float* cb   = (const float*)d_in[4];
    const float* dtb  = (const float*)d_in[5];
    const float* alog = (const float*)d_in[6];
    const float* Dp   = (const float*)d_in[7];
    const float* mnw  = (const float*)d_in[8];
    const float* ow   = (const float*)d_in[9];
    const float* lnw  = (const float*)d_in[10];
    const float* nfw  = (const float*)d_in[11];
    float* out = (float*)d_out;

    float *px, *pzx;
    __nv_bfloat16 *pinwh, *pinwl, *powh, *powl, *puh, *pul, *pynh, *pynl;
    __half *pembhalf, *puhalf;
    cudaGetSymbolAddress((void**)&px,   g_x);
    cudaGetSymbolAddress((void**)&pzx,  g_zx);
    cudaGetSymbolAddress((void**)&pinwh, g_inwh);
    cudaGetSymbolAddress((void**)&pinwl, g_inwl);
    cudaGetSymbolAddress((void**)&powh,  g_owh);
    cudaGetSymbolAddress((void**)&powl,  g_owl);
    cudaGetSymbolAddress((void**)&puh,   g_uh);
    cudaGetSymbolAddress((void**)&pul,   g_ul);
    cudaGetSymbolAddress((void**)&pynh,  g_ynh);
    cudaGetSymbolAddress((void**)&pynl,  g_ynl);
    cudaGetSymbolAddress((void**)&pembhalf, g_embhalf);
    cudaGetSymbolAddress((void**)&puhalf,   g_uhalf);

    const int CHUNK_SMEM = (64*129*2 + 64*65*2 + 128) * (int)sizeof(float);
    const int YOFF_SMEM  = (64*129*2 + 64) * (int)sizeof(float);
    cudaFuncSetAttribute(chunk_kernel, cudaFuncAttributeMaxDynamicSharedMemorySize, CHUNK_SMEM);
    cudaFuncSetAttribute(yoff_kernel,  cudaFuncAttributeMaxDynamicSharedMemorySize, YOFF_SMEM);
    cudaFuncSetAttribute(gemm_tc,      cudaFuncAttributeMaxDynamicSharedMemorySize, GEMM_SMEM);
    cudaFuncSetAttribute(gemm_half,    cudaFuncAttributeMaxDynamicSharedMemorySize, GEMMH_SMEM);

    // weight prep
    convert_half_kernel<<<(NV*DM/4 + 255)/256, 256>>>(emb, pembhalf, NV*DM/4);
    split_kernel<<<(NL*DPROJ*DM/4 + 255)/256, 256>>>(inw, pinwh, pinwl, NL*DPROJ*DM/4);
    split_kernel<<<(NL*DM*DIN/4 + 255)/256, 256>>>(ow, powh, powl, NL*DM*DIN/4);

    embed_kernel<<<SEQ, 256>>>(ids, emb);

    for (int i = 0; i < NL; i++) {
        rmsnorm_split_kernel<<<SEQ, 256>>>(px, lnw + (size_t)i*DM, puh, pul, DM);
        gemm_tc<<<dim3(SEQ/128, (DPROJ + 127)/128), 256, GEMM_SMEM>>>(
            puh, pul, pinwh + (size_t)i*DPROJ*DM, pinwl + (size_t)i*DPROJ*DM,
            nullptr, pzx, SEQ, DPROJ, DM);
        conv_kernel<<<(SEQ*CONVD + 255)/256, 256>>>(cw + (size_t)i*CONVD*4, cb + (size_t)i*CONVD);
        dt_kernel<<<(SEQ*NH + 255)/256, 256>>>(dtb + i*NH, alog + i*NH);
        chunk_kernel<<<dim3(NCH, NH), 256, CHUNK_SMEM>>>();
        scan_kernel<<<NH*HD*DSTATE/256, 256>>>();
        yoff_kernel<<<dim3(NCH, NH), 256, YOFF_SMEM>>>(Dp + i*NH);
        gated_rmsnorm_kernel<<<SEQ, 256>>>(mnw + (size_t)i*DIN);
        gemm_tc<<<dim3(SEQ/128, DM/128), 256, GEMM_SMEM>>>(
            pynh, pynl, powh + (size_t)i*DM*DIN, powl + (size_t)i*DM*DIN,
            px, px, SEQ, DM, DIN);
    }

    rmsnorm_half_kernel<<<SEQ, 256>>>(px, nfw, puhalf, DM);
    gemm_half<<<dim3(SEQ/128, (NV + 127)/128), 256, GEMMH_SMEM>>>(
        puhalf, pembhalf, out, SEQ, NV, DM);
}